// round 15
// baseline (speedup 1.0000x reference)
#include <cuda_runtime.h>
#include <cuda_bf16.h>
#include <math.h>
#include <stdint.h>

#define SEQ 6912
#define DIM 1536
#define NH  12
#define HD  128
#define Fg  12
#define Hg  24
#define Wg  24
#define FK  288
#define EPS_NORM 1e-6f
#define CAPF (1.0f/1.000001f)

__device__ float g_q[SEQ * DIM];
__device__ float g_k[SEQ * DIM];
__device__ float g_v[SEQ * DIM];
__device__ float g_attn[SEQ * DIM];
__device__ float g_xr[SEQ * DIM];
__device__ float g_w4[4 * DIM * DIM];
__device__ __nv_bfloat16 g_qh[SEQ * DIM], g_ql[SEQ * DIM];
__device__ __nv_bfloat16 g_kh[SEQ * DIM], g_kl[SEQ * DIM];
__device__ __nv_bfloat16 g_vh[SEQ * DIM], g_vl[SEQ * DIM];
__device__ __nv_bfloat16 g_ah[(size_t)NH * Fg * Wg * FK * HD];
__device__ __nv_bfloat16 g_al[(size_t)NH * Fg * Wg * FK * HD];
__device__ __nv_bfloat16 g_yh[(size_t)NH * Fg * Wg * FK * HD];
__device__ __nv_bfloat16 g_yl[(size_t)NH * Fg * Wg * FK * HD];
__device__ float g_cL[(size_t)NH * Fg * Wg * FK];

__device__ __forceinline__ void cp16(void* dst, const void* src) {
    uint32_t d = (uint32_t)__cvta_generic_to_shared(dst);
    asm volatile("cp.async.cg.shared.global [%0], [%1], 16;\n" :: "r"(d), "l"(src));
}
__device__ __forceinline__ void cp16s(uint32_t dst, const void* src) {
    asm volatile("cp.async.cg.shared.global [%0], [%1], 16;\n" :: "r"(dst), "l"(src));
}
__device__ __forceinline__ float tf32f(float x) {
    uint32_t r;
    asm("cvt.rna.tf32.f32 %0, %1;\n" : "=r"(r) : "f"(x));
    return __uint_as_float(r);
}
__device__ __forceinline__ uint32_t packbf(float a, float b) {
    return (uint32_t)__bfloat16_as_ushort(__float2bfloat16(a)) |
           ((uint32_t)__bfloat16_as_ushort(__float2bfloat16(b)) << 16);
}
__device__ __forceinline__ void split2(float f0, float f1, uint32_t& hi, uint32_t& lo) {
    const __nv_bfloat16 h0 = __float2bfloat16(f0);
    const __nv_bfloat16 h1 = __float2bfloat16(f1);
    hi = (uint32_t)__bfloat16_as_ushort(h0) | ((uint32_t)__bfloat16_as_ushort(h1) << 16);
    lo = packbf(f0 - __bfloat162float(h0), f1 - __bfloat162float(h1));
}

__global__ __launch_bounds__(256) void round_permute(
    const float* __restrict__ in, float* __restrict__ out, int n8)
{
    const int i = blockIdx.x * 256 + threadIdx.x;
    if (i >= n8) return;
    const float4* p = reinterpret_cast<const float4*>(in) + (size_t)i * 2;
    const float4 x0 = p[0], x1 = p[1];
    float4 y0 = make_float4(tf32f(x0.x), tf32f(x1.x), tf32f(x0.y), tf32f(x1.y));
    float4 y1 = make_float4(tf32f(x0.z), tf32f(x1.z), tf32f(x0.w), tf32f(x1.w));
    float4* q = reinterpret_cast<float4*>(out) + (size_t)i * 2;
    q[0] = y0; q[1] = y1;
}

__global__ __launch_bounds__(256) void round_permute_w4(
    const float* __restrict__ W0, const float* __restrict__ W1,
    const float* __restrict__ W2, const float* __restrict__ W3,
    float* __restrict__ out, int n8)
{
    const int t = blockIdx.y;
    const float* src = (t == 0) ? W0 : (t == 1) ? W1 : (t == 2) ? W2 : W3;
    const int i = blockIdx.x * 256 + threadIdx.x;
    if (i >= n8) return;
    const float4* p = reinterpret_cast<const float4*>(src) + (size_t)i * 2;
    const float4 x0 = p[0], x1 = p[1];
    float4 y0 = make_float4(tf32f(x0.x), tf32f(x1.x), tf32f(x0.y), tf32f(x1.y));
    float4 y1 = make_float4(tf32f(x0.z), tf32f(x1.z), tf32f(x0.w), tf32f(x1.w));
    float4* q = reinterpret_cast<float4*>(out + (size_t)t * DIM * DIM) + (size_t)i * 2;
    q[0] = y0; q[1] = y1;
}

__global__ __launch_bounds__(256) void split_v(int n2)
{
    const int i = blockIdx.x * 256 + threadIdx.x;
    if (i >= n2) return;
    const float2 x = reinterpret_cast<const float2*>(g_v)[i];
    uint32_t hi, lo;
    split2(x.x, x.y, hi, lo);
    *reinterpret_cast<uint32_t*>(g_vh + (size_t)i * 2) = hi;
    *reinterpret_cast<uint32_t*>(g_vl + (size_t)i * 2) = lo;
}

// ---- tf32 GEMM, BK=32, dynamic smem, fused over blockIdx.z (up to 3 mats) ---
#define GPAD 40
#define GSTG (128 * GPAD)            // words per array per stage
#define GEMM_SM (4 * GSTG * 4)       // 81920 bytes -> 2 CTAs/SM

__global__ __launch_bounds__(256) void gemm_tf32x(
    const float* __restrict__ A,
    const float* __restrict__ W0, const float* __restrict__ W1,
    const float* __restrict__ W2,
    const float* __restrict__ b0v, const float* __restrict__ b1v,
    const float* __restrict__ b2v,
    float* __restrict__ o0p, float* __restrict__ o1p, float* __restrict__ o2p,
    int M, int K, int O)
{
    extern __shared__ float smf[];
    const int z = blockIdx.z;
    const float* W   = (z == 0) ? W0 : (z == 1) ? W1 : W2;
    const float* bias = (z == 0) ? b0v : (z == 1) ? b1v : b2v;
    float* out = (z == 0) ? o0p : (z == 1) ? o1p : o2p;

    const int tid = threadIdx.x, lane = tid & 31, warp = tid >> 5;
    const int gid = lane >> 2, tg = lane & 3;
    const int wm = (warp & 1) * 64, wn = (warp >> 1) * 32;
    const int m0 = blockIdx.y * 128, o0 = blockIdx.x * 128;

    float acc[4][4][4];
#pragma unroll
    for (int mt = 0; mt < 4; mt++)
#pragma unroll
        for (int nt = 0; nt < 4; nt++)
#pragma unroll
            for (int r = 0; r < 4; r++) acc[mt][nt][r] = 0.f;

    const int nIter = K / 32;    // 48

#define GLOAD(S, IT) do { \
    const int k0 = (IT) * 32; \
    float* As_ = smf + (S) * 2 * GSTG; \
    float* Ws_ = As_ + GSTG; \
    _Pragma("unroll") \
    for (int q = 0; q < 4; q++) { \
        const int idx = tid + q * 256; \
        const int row = idx >> 3, c4 = (idx & 7) * 4; \
        cp16(&As_[row * GPAD + c4], A + (size_t)(m0 + row) * K + k0 + c4); \
        cp16(&Ws_[row * GPAD + c4], W + (size_t)(o0 + row) * K + k0 + c4); \
    } \
    asm volatile("cp.async.commit_group;\n"); \
} while (0)

    GLOAD(0, 0);

    for (int it = 0; it < nIter; ++it) {
        const int b = it & 1;
        if (it + 1 < nIter) {
            GLOAD(b ^ 1, it + 1);
            asm volatile("cp.async.wait_group 1;\n");
        } else {
            asm volatile("cp.async.wait_group 0;\n");
        }
        __syncthreads();
        const float* as = smf + b * 2 * GSTG;
        const float* ws = as + GSTG;
#pragma unroll
        for (int kk = 0; kk < 32; kk += 8) {
            uint32_t a[4][4], bb[4][2];
#pragma unroll
            for (int mt = 0; mt < 4; mt++) {
                const int mr = wm + mt * 16 + gid;
                const float2 pa = *reinterpret_cast<const float2*>(&as[mr * GPAD + kk + 2 * tg]);
                const float2 pb = *reinterpret_cast<const float2*>(&as[(mr + 8) * GPAD + kk + 2 * tg]);
                a[mt][0] = __float_as_uint(pa.x); a[mt][1] = __float_as_uint(pb.x);
                a[mt][2] = __float_as_uint(pa.y); a[mt][3] = __float_as_uint(pb.y);
            }
#pragma unroll
            for (int nt = 0; nt < 4; nt++) {
                const int nr = wn + nt * 8 + gid;
                const float2 pw = *reinterpret_cast<const float2*>(&ws[nr * GPAD + kk + 2 * tg]);
                bb[nt][0] = __float_as_uint(pw.x); bb[nt][1] = __float_as_uint(pw.y);
            }
#pragma unroll
            for (int mt = 0; mt < 4; mt++)
#pragma unroll
                for (int nt = 0; nt < 4; nt++)
                    asm volatile(
                        "mma.sync.aligned.m16n8k8.row.col.f32.tf32.tf32.f32 "
                        "{%0,%1,%2,%3}, {%4,%5,%6,%7}, {%8,%9}, {%0,%1,%2,%3};\n"
                        : "+f"(acc[mt][nt][0]), "+f"(acc[mt][nt][1]),
                          "+f"(acc[mt][nt][2]), "+f"(acc[mt][nt][3])
                        : "r"(a[mt][0]), "r"(a[mt][1]), "r"(a[mt][2]), "r"(a[mt][3]),
                          "r"(bb[nt][0]), "r"(bb[nt][1]));
        }
        __syncthreads();
    }
#pragma unroll
    for (int mt = 0; mt < 4; mt++) {
        const int m = m0 + wm + mt * 16 + gid;
#pragma unroll
        for (int nt = 0; nt < 4; nt++) {
            const int o = o0 + wn + nt * 8 + tg * 2;
            const float c0 = bias[o], c1 = bias[o + 1];
            *reinterpret_cast<float2*>(&out[(size_t)m * O + o]) =
                make_float2(acc[mt][nt][0] + c0, acc[mt][nt][1] + c1);
            *reinterpret_cast<float2*>(&out[(size_t)(m + 8) * O + o]) =
                make_float2(acc[mt][nt][2] + c0, acc[mt][nt][3] + c1);
        }
    }
}

__global__ __launch_bounds__(256) void norm_rope2(
    const float* __restrict__ qd, const float* __restrict__ kd,
    const float* __restrict__ gqv, const float* __restrict__ gkv,
    const float* __restrict__ freqs, float scale)
{
    const int s = blockIdx.x, isK = blockIdx.y;
    const float* row = (isK ? kd : qd) + (size_t)s * DIM;
    __nv_bfloat16* dh = (isK ? g_kh : g_qh) + (size_t)s * DIM;
    __nv_bfloat16* dl = (isK ? g_kl : g_ql) + (size_t)s * DIM;
    const float* g = isK ? gkv : gqv;
    const int tid = threadIdx.x;

    float ss = 0.f;
    for (int c = tid; c < DIM; c += 256) { float v = row[c]; ss += v * v; }
#pragma unroll
    for (int off = 16; off; off >>= 1) ss += __shfl_xor_sync(~0u, ss, off);
    __shared__ float red[8];
    __shared__ float s_rms;
    if ((tid & 31) == 0) red[tid >> 5] = ss;
    __syncthreads();
    if (tid == 0) {
        float t = 0.f;
#pragma unroll
        for (int i = 0; i < 8; i++) t += red[i];
        s_rms = rsqrtf(t / (float)DIM + EPS_NORM);
    }
    __syncthreads();
    const float rms = s_rms;
    const int fidx = s / 576, rem = s % 576, hidx = rem / 24, widx = rem % 24;

    for (int p = tid; p < DIM / 2; p += 256) {
        const int n = p >> 6, m = p & 63;
        const int pos = (m < 22) ? fidx : (m < 43) ? hidx : widx;
        float sn, cs;
        sincosf(freqs[pos * 64 + m], &sn, &cs);
        const int c0 = n * HD + 2 * m;
        const float xr = row[c0] * rms * g[c0];
        const float xi = row[c0 + 1] * rms * g[c0 + 1];
        const float y0 = (xr * cs - xi * sn) * scale;
        const float y1 = (xr * sn + xi * cs) * scale;
        uint32_t hi, lo;
        split2(y0, y1, hi, lo);
        *reinterpret_cast<uint32_t*>(dh + c0) = hi;
        *reinterpret_cast<uint32_t*>(dl + c0) = lo;
    }
}

#define MMAB(C,A0,A1,A2,A3,B0,B1) \
    asm volatile("mma.sync.aligned.m16n8k16.row.col.f32.bf16.bf16.f32 " \
        "{%0,%1,%2,%3}, {%4,%5,%6,%7}, {%8,%9}, {%0,%1,%2,%3};\n" \
        : "+f"((C)[0]), "+f"((C)[1]), "+f"((C)[2]), "+f"((C)[3]) \
        : "r"(A0), "r"(A1), "r"(A2), "r"(A3), "r"(B0), "r"(B1))

#define SA_SMEM (16768 * 4)

__global__ __launch_bounds__(256) void stageA_mma()
{
    const int kb = blockIdx.x, f = blockIdx.y, h = blockIdx.z;
    extern __shared__ uint32_t smw[];
    uint32_t* KH = smw;
    uint32_t* KL = smw + 1632;
    uint32_t* VH = smw + 3264;
    uint32_t* VL = smw + 4896;
    uint32_t* TKH = smw + 6528;
    uint32_t* TKL = smw + 9088;
    uint32_t* TVH = smw + 11648;
    uint32_t* TVL = smw + 14208;

    const int tid = threadIdx.x, lane = tid & 31, w = tid >> 5;
    const int gid = lane >> 2, tg = lane & 3;
    const int skb = f * 576 + kb * 24;

    for (int idx = tid; idx < 24 * 64; idx += 256) {
        const int l = idx >> 6, wd = idx & 63;
        const size_t e = (size_t)(skb + l) * DIM + h * HD + wd * 2;
        KH[l * 68 + wd] = *reinterpret_cast<const uint32_t*>(g_kh + e);
        KL[l * 68 + wd] = *reinterpret_cast<const uint32_t*>(g_kl + e);
        VH[l * 68 + wd] = *reinterpret_cast<const uint32_t*>(g_vh + e);
        VL[l * 68 + wd] = *reinterpret_cast<const uint32_t*>(g_vl + e);
    }
    __syncthreads();
    {
        const ushort* sK = (const ushort*)KH;
        const ushort* sk = (const ushort*)KL;
        const ushort* sV = (const ushort*)VH;
        const ushort* sv = (const ushort*)VL;
        for (int idx = tid; idx < 128 * 12; idx += 256) {
            const int d = idx / 12, wv = idx % 12, l = 2 * wv;
            TKH[d * 20 + wv] = (uint32_t)sK[l * 136 + d] | ((uint32_t)sK[(l + 1) * 136 + d] << 16);
            TKL[d * 20 + wv] = (uint32_t)sk[l * 136 + d] | ((uint32_t)sk[(l + 1) * 136 + d] << 16);
            TVH[d * 20 + wv] = (uint32_t)sV[l * 136 + d] | ((uint32_t)sV[(l + 1) * 136 + d] << 16);
            TVL[d * 20 + wv] = (uint32_t)sv[l * 136 + d] | ((uint32_t)sv[(l + 1) * 136 + d] << 16);
        }
    }
    __syncthreads();

    for (int mt = w; mt < 18; mt += 8) {
        const int r0 = mt * 16 + gid, r1 = r0 + 8;
        const int a0i = r0 / 24, j0 = r0 - a0i * 24;
        const int a1i = r1 / 24, j1 = r1 - a1i * 24;
        const uint32_t* q0h = (const uint32_t*)(g_qh + (size_t)(a0i * 576 + kb * 24 + j0) * DIM + h * HD);
        const uint32_t* q0l = (const uint32_t*)(g_ql + (size_t)(a0i * 576 + kb * 24 + j0) * DIM + h * HD);
        const uint32_t* q1h = (const uint32_t*)(g_qh + (size_t)(a1i * 576 + kb * 24 + j1) * DIM + h * HD);
        const uint32_t* q1l = (const uint32_t*)(g_ql + (size_t)(a1i * 576 + kb * 24 + j1) * DIM + h * HD);

        float c[3][4];
#pragma unroll
        for (int nt = 0; nt < 3; nt++)
            c[nt][0] = c[nt][1] = c[nt][2] = c[nt][3] = 0.f;
#pragma unroll
        for (int kk = 0; kk < 8; kk++) {
            const int wa = kk * 8 + tg;
            const uint32_t ah0 = q0h[wa], ah1 = q1h[wa], ah2 = q0h[wa + 4], ah3 = q1h[wa + 4];
            const uint32_t al0 = q0l[wa], al1 = q1l[wa], al2 = q0l[wa + 4], al3 = q1l[wa + 4];
#pragma unroll
            for (int nt = 0; nt < 3; nt++) {
                const int nb = (nt * 8 + gid) * 68 + wa;
                const uint32_t bh0 = KH[nb], bh1 = KH[nb + 4];
                const uint32_t bl0 = KL[nb], bl1 = KL[nb + 4];
                MMAB(c[nt], ah0, ah1, ah2, ah3, bh0, bh1);
                MMAB(c[nt], ah0, ah1, ah2, ah3, bl0, bl1);
                MMAB(c[nt], al0, al1, al2, al3, bh0, bh1);
            }
        }

        float m0 = -1e30f, m1 = -1e30f;
#pragma unroll
        for (int nt = 0; nt < 3; nt++) {
#pragma unroll
            for (int r = 0; r < 4; r++) c[nt][r] *= CAPF;
            m0 = fmaxf(m0, fmaxf(c[nt][0], c[nt][1]));
            m1 = fmaxf(m1, fmaxf(c[nt][2], c[nt][3]));
        }
        m0 = fmaxf(m0, __shfl_xor_sync(~0u, m0, 1));
        m0 = fmaxf(m0, __shfl_xor_sync(~0u, m0, 2));
        m1 = fmaxf(m1, __shfl_xor_sync(~0u, m1, 1));
        m1 = fmaxf(m1, __shfl_xor_sync(~0u, m1, 2));
        float S0 = 0.f, E0 = 0.f, S1 = 0.f, E1 = 0.f, R[3][4];
#pragma unroll
        for (int nt = 0; nt < 3; nt++) {
            const float t0 = c[nt][0] - m0, t1 = c[nt][1] - m0;
            const float t2 = c[nt][2] - m1, t3 = c[nt][3] - m1;
            const float e0 = expf(t0), e1 = expf(t1), e2 = expf(t2), e3 = expf(t3);
            S0 += e0 + e1; E0 += e0 * t0 + e1 * t1;
            S1 += e2 + e3; E1 += e2 * t2 + e3 * t3;
            R[nt][0] = e0; R[nt][1] = e1; R[nt][2] = e2; R[nt][3] = e3;
        }
        S0 += __shfl_xor_sync(~0u, S0, 1); S0 += __shfl_xor_sync(~0u, S0, 2);
        E0 += __shfl_xor_sync(~0u, E0, 1); E0 += __shfl_xor_sync(~0u, E0, 2);
        S1 += __shfl_xor_sync(~0u, S1, 1); S1 += __shfl_xor_sync(~0u, S1, 2);
        E1 += __shfl_xor_sync(~0u, E1, 1); E1 += __shfl_xor_sync(~0u, E1, 2);
        const float i0 = 1.f / S0, i1 = 1.f / S1;

        const size_t rb0 = ((size_t)((h * 12 + a0i) * 24 + j0)) * FK + (f * 24 + kb);
        const size_t rb1 = ((size_t)((h * 12 + a1i) * 24 + j1)) * FK + (f * 24 + kb);
        if (tg == 0) {
            g_cL[rb0] = E0 * i0 - logf(S0);
            g_cL[rb1] = E1 * i1 - logf(S1);
        }

        uint32_t Ph[3], Pr[3], Ql[3], Qr[3];
#pragma unroll
        for (int nt = 0; nt < 3; nt++) {
            split2(R[nt][0] * i0, R[nt][1] * i0, Ph[nt], Ql[nt]);
            split2(R[nt][2] * i1, R[nt][3] * i1, Pr[nt], Qr[nt]);
        }

        const size_t wb0 = rb0 * 64, wb1 = rb1 * 64;
#pragma unroll
        for (int nt = 0; nt < 16; nt++) {
            const int nb = (nt * 8 + gid) * 20;
            float aa[4] = {0,0,0,0}, ay[4] = {0,0,0,0};
            uint32_t b0 = TKH[nb + tg], b1 = TKH[nb + 4 + tg];
            MMAB(aa, Ph[0], Pr[0], Ph[1], Pr[1], b0, b1);
            MMAB(aa, Ql[0], Qr[0], Ql[1], Qr[1], b0, b1);
            b0 = TKL[nb + tg]; b1 = TKL[nb + 4 + tg];
            MMAB(aa, Ph[0], Pr[0], Ph[1], Pr[1], b0, b1);
            b0 = TKH[nb + 8 + tg];
            MMAB(aa, Ph[2], Pr[2], 0u, 0u, b0, b0);
            MMAB(aa, Ql[2], Qr[2], 0u, 0u, b0, b0);
            b0 = TKL[nb + 8 + tg];
            MMAB(aa, Ph[2], Pr[2], 0u, 0u, b0, b0);

            b0 = TVH[nb + tg]; b1 = TVH[nb + 4 + tg];
            MMAB(ay, Ph[0], Pr[0], Ph[1], Pr[1], b0, b1);
            MMAB(ay, Ql[0], Qr[0], Ql[1], Qr[1], b0, b1);
            b0 = TVL[nb + tg]; b1 = TVL[nb + 4 + tg];
            MMAB(ay, Ph[0], Pr[0], Ph[1], Pr[1], b0, b1);
            b0 = TVH[nb + 8 + tg];
            MMAB(ay, Ph[2], Pr[2], 0u, 0u, b0, b0);
            MMAB(ay, Ql[2], Qr[2], 0u, 0u, b0, b0);
            b0 = TVL[nb + 8 + tg];
            MMAB(ay, Ph[2], Pr[2], 0u, 0u, b0, b0);

            const int wi = nt * 4 + tg;
            uint32_t hi, lo;
            split2(aa[0], aa[1], hi, lo);
            ((uint32_t*)g_ah)[wb0 + wi] = hi; ((uint32_t*)g_al)[wb0 + wi] = lo;
            split2(aa[2], aa[3], hi, lo);
            ((uint32_t*)g_ah)[wb1 + wi] = hi; ((uint32_t*)g_al)[wb1 + wi] = lo;
            split2(ay[0], ay[1], hi, lo);
            ((uint32_t*)g_yh)[wb0 + wi] = hi; ((uint32_t*)g_yl)[wb0 + wi] = lo;
            split2(ay[2], ay[3], hi, lo);
            ((uint32_t*)g_yh)[wb1 + wi] = hi; ((uint32_t*)g_yl)[wb1 + wi] = lo;
        }
    }
}

// ---------------- Stage B (round-14 version, 2 CTAs/SM) ----------------------
#define QHo 0
#define QLo 1632
#define CLo 3264
#define BLo 3552
#define LmHo 10560
#define LmLo 14112
#define Y0H 17664
#define Y0L 19840
#define Y1H 22016
#define Y1L 24192
#define SB_SMEM (26368 * 4)

__global__ __launch_bounds__(256) void stageB_mma()
{
    const int j = blockIdx.x, a = blockIdx.y, h = blockIdx.z;
    extern __shared__ uint32_t smw[];
    uint32_t sb;
    asm("{ .reg .u64 t; cvta.to.shared.u64 t, %1; cvt.u32.u64 %0, t; }"
        : "=r"(sb) : "l"(smw));
    float* bl = (float*)(smw + BLo);
    float* cls = (float*)(smw + CLo);

    const int tid = threadIdx.x, lane = tid & 31, w = tid >> 5;
    const int gid = lane >> 2, tg = lane & 3;
    const size_t base = (size_t)(h * 12 + a) * 24 + j;
    const size_t albase = base * FK * HD;
    const size_t clbase = base * FK;

#define LOADY32(BH, BL2, C) do { \
    _Pragma("unroll") \
    for (int t5 = 0; t5 < 2; t5++) { \
        const int idx = tid + t5 * 256; \
        const int r = idx >> 4, seg = idx & 15; \
        const size_t so = albase + (size_t)((C) * 32 + r) * HD + seg * 8; \
        cp16s(sb + ((BH) + r * 68) * 4 + seg * 16, g_yh + so); \
        cp16s(sb + ((BL2) + r * 68) * 4 + seg * 16, g_yl + so); \
    } \
    asm volatile("cp.async.commit_group;\n"); \
} while (0)

    LOADY32(Y0H, Y0L, 0);

    for (int idx = tid; idx < 24 * 64; idx += 256) {
        const int i = idx >> 6, wd = idx & 63;
        const size_t e = (size_t)(a * 576 + i * 24 + j) * DIM + h * HD + wd * 2;
        smw[QHo + i * 68 + wd] = *reinterpret_cast<const uint32_t*>(g_qh + e);
        smw[QLo + i * 68 + wd] = *reinterpret_cast<const uint32_t*>(g_ql + e);
    }
    for (int idx = tid; idx < FK; idx += 256) cls[idx] = g_cL[clbase + idx];
    __syncthreads();

    for (int mt = w; mt < 18; mt += 8) {
        const int fk0 = mt * 16 + gid, fk1 = fk0 + 8;
        const uint32_t* A0h = (const uint32_t*)g_ah + albase / 2 + fk0 * 64;
        const uint32_t* A0l = (const uint32_t*)g_al + albase / 2 + fk0 * 64;
        const uint32_t* A1h = (const uint32_t*)g_ah + albase / 2 + fk1 * 64;
        const uint32_t* A1l = (const uint32_t*)g_al + albase / 2 + fk1 * 64;

        float c[3][4];
#pragma unroll
        for (int nt = 0; nt < 3; nt++)
            c[nt][0] = c[nt][1] = c[nt][2] = c[nt][3] = 0.f;
#pragma unroll
        for (int kk = 0; kk < 8; kk++) {
            const int wa = kk * 8 + tg;
            const uint32_t ah0 = A0h[wa], ah1 = A1h[wa], ah2 = A0h[wa + 4], ah3 = A1h[wa + 4];
            const uint32_t al0 = A0l[wa], al1 = A1l[wa], al2 = A0l[wa + 4], al3 = A1l[wa + 4];
#pragma unroll
            for (int nt = 0; nt < 3; nt++) {
                const int nb = QHo + (nt * 8 + gid) * 68 + wa;
                const uint32_t bh0 = smw[nb], bh1 = smw[nb + 4];
                const uint32_t bl0 = smw[nb + (QLo - QHo)], bl1 = smw[nb + (QLo - QHo) + 4];
                MMAB(c[nt], ah0, ah1, ah2, ah3, bh0, bh1);
                MMAB(c[nt], ah0, ah1, ah2, ah3, bl0, bl1);
                MMAB(c[nt], al0, al1, al2, al3, bh0, bh1);
            }
        }
        const float cl0 = cls[fk0], cl1 = cls[fk1];
#pragma unroll
        for (int nt = 0; nt < 3; nt++) {
            const int i0 = nt * 8 + 2 * tg;
            bl[i0 * 292 + fk0]       = c[nt][0] - cl0;
            bl[(i0 + 1) * 292 + fk0] = c[nt][1] - cl0;
            bl[i0 * 292 + fk1]       = c[nt][2] - cl1;
            bl[(i0 + 1) * 292 + fk1] = c[nt][3] - cl1;
        }
    }
    __syncthreads();

    for (int ri = w; ri < 24; ri += 8) {
        float* rowp = bl + ri * 292;
        float v[9], mx = -INFINITY;
#pragma unroll
        for (int q = 0; q < 9; q++) { v[q] = rowp[lane + q * 32]; mx = fmaxf(mx, v[q]); }
#pragma unroll
        for (int off = 16; off; off >>= 1) mx = fmaxf(mx, __shfl_xor_sync(~0u, mx, off));
        float s = 0.f;
#pragma unroll
        for (int q = 0; q < 9; q++) { v[q] = expf(v[q] - mx); s += v[q]; }
#pragma unroll
        for (int off = 16; off; off >>= 1) s += __shfl_xor_sync(~0u, s, off);
        const float inv = 1.f / s;
#pragma unroll
        for (int q = 0; q < 9; q++) rowp[lane + q * 32] = v[q] * inv;
        __syncwarp();
        for (int w2 = lane; w2 < 144; w2 += 32) {
            const float f0 = rowp[2 * w2], f1 = rowp[2 * w2 + 1];
            uint32_t hi, lo;
            split2(f0, f1, hi, lo);
            smw[LmHo + ri * 148 + w2] = hi;
            smw[LmLo + ri * 148 + w2] = lo;
        }
    }
    __syncthreads();

    float cc[2][2][4];
#pragma unroll
    for (int m = 0; m < 2; m++)
#pragma unroll
        for (int t = 0; t < 2; t++)
#pragma unroll
            for (int r = 0; r < 4; r++) cc[m][t][r] = 0.f;

#define YCHUNK32(BH, BL2, C) do { \
    _Pragma("unroll") \
    for (int kkl = 0; kkl < 2; kkl++) { \
        const int wa = ((C) * 2 + kkl) * 8 + tg; \
        uint32_t Ah[2][4], Al2[2][4]; \
        _Pragma("unroll") \
        for (int m = 0; m < 2; m++) { \
            int r2w = m * 16 + 8 + gid; if (r2w > 23) r2w = 23; \
            const int rb = (m * 16 + gid) * 148, rb8 = r2w * 148; \
            Ah[m][0] = smw[LmHo + rb + wa];     Ah[m][1] = smw[LmHo + rb8 + wa]; \
            Ah[m][2] = smw[LmHo + rb + wa + 4]; Ah[m][3] = smw[LmHo + rb8 + wa + 4]; \
            Al2[m][0] = smw[LmLo + rb + wa];     Al2[m][1] = smw[LmLo + rb8 + wa]; \
            Al2[m][2] = smw[LmLo + rb + wa + 4]; Al2[m][3] = smw[LmLo + rb8 + wa + 4]; \
        } \
        _Pragma("unroll") \
        for (int t = 0; t < 2; t++) { \
            const int nn = w * 2 + t; \
            const uint32_t ad = sb + ((BH) + (kkl * 16 + (lane & 15)) * 68 + nn * 4) * 4; \
            uint32_t bh0, bh1, bl0, bl1; \
            asm volatile("ldmatrix.sync.aligned.m8n8.x2.trans.shared.b16 {%0,%1}, [%2];" \
                : "=r"(bh0), "=r"(bh1) : "r"(ad)); \
            asm volatile("ldmatrix.sync.aligned.m8n8.x2.trans.shared.b16 {%0,%1}, [%2];" \
                : "=r"(bl0), "=r"(bl1) : "r"(ad + ((BL2) - (BH)) * 4)); \
            _Pragma("unroll") \
            for (int m = 0; m < 2; m++) { \
                MMAB(cc[m][t], Ah[m][0], Ah[m][1], Ah[m][2], Ah[m][3], bh0, bh1); \
                MMAB(cc[m][t], Al2[m][0], Al2[m][1], Al2[m][2], Al2[m][3], bh0, bh1); \
                MMAB(cc[m][t], Ah[m][0], Ah[m][1], Ah[m][2], Ah[m][3], bl0, bl1); \
            } \
        } \
    } \
} while (0)

    LOADY32(Y1H, Y1L, 1);
    for (int c = 0; c < 9; ++c) {
        if (c < 8) { asm volatile("cp.async.wait_group 1;\n"); }
        else       { asm volatile("cp.async.wait_group 0;\n"); }
        __syncthreads();
        if (c & 1) { YCHUNK32(Y1H, Y1L, c); } else { YCHUNK32(Y0H, Y0L, c); }
        __syncthreads();
        if (c + 2 < 9) {
            if (c & 1) { LOADY32(Y1H, Y1L, c + 2); } else { LOADY32(Y0H, Y0L, c + 2); }
        }
    }

#pragma unroll
    for (int t = 0; t < 2; t++) {
        const int d0 = (w * 2 + t) * 8 + 2 * tg;
        const size_t e0 = (size_t)(a * 576 + gid * 24 + j) * DIM + h * HD + d0;
        const size_t e1 = (size_t)(a * 576 + (gid + 8) * 24 + j) * DIM + h * HD + d0;
        const size_t e2 = (size_t)(a * 576 + (gid + 16) * 24 + j) * DIM + h * HD + d0;
        *reinterpret_cast<float2*>(&g_attn[e0]) = make_float2(cc[0][t][0], cc[0][t][1]);
        *reinterpret_cast<float2*>(&g_attn[e1]) = make_float2(cc[0][t][2], cc[0][t][3]);
        *reinterpret_cast<float2*>(&g_attn[e2]) = make_float2(cc[1][t][0], cc[1][t][1]);
    }
}

extern "C" void kernel_launch(void* const* d_in, const int* in_sizes, int n_in,
                              void* d_out, int out_size)
{
    (void)in_sizes; (void)n_in; (void)out_size;
    const float* x  = (const float*)d_in[0];
    const float* Wq = (const float*)d_in[1];
    const float* bq = (const float*)d_in[2];
    const float* Wk = (const float*)d_in[3];
    const float* bk = (const float*)d_in[4];
    const float* Wv = (const float*)d_in[5];
    const float* bv = (const float*)d_in[6];
    const float* Wo = (const float*)d_in[7];
    const float* bo = (const float*)d_in[8];
    const float* gq = (const float*)d_in[9];
    const float* gk = (const float*)d_in[10];
    const float* fr = (const float*)d_in[11];
    float* out = (float*)d_out;

    float *qp, *kp, *vp, *ap, *xr, *w4;
    cudaGetSymbolAddress((void**)&qp, g_q);
    cudaGetSymbolAddress((void**)&kp, g_k);
    cudaGetSymbolAddress((void**)&vp, g_v);
    cudaGetSymbolAddress((void**)&ap, g_attn);
    cudaGetSymbolAddress((void**)&xr, g_xr);
    cudaGetSymbolAddress((void**)&w4, g_w4);

    cudaFuncSetAttribute(gemm_tf32x,
        cudaFuncAttributeMaxDynamicSharedMemorySize, GEMM_SM);
    cudaFuncSetAttribute(stageA_mma,
        cudaFuncAttributeMaxDynamicSharedMemorySize, SA_SMEM);
    cudaFuncSetAttribute(stageB_mma,
        cudaFuncAttributeMaxDynamicSharedMemorySize, SB_SMEM);

    const int nx8 = SEQ * DIM / 8;
    const int nw8 = DIM * DIM / 8;
    const int WSZ = DIM * DIM;

    round_permute<<<(nx8 + 255) / 256, 256>>>(x, xr, nx8);
    round_permute_w4<<<dim3((nw8 + 255) / 256, 4), 256>>>(Wq, Wk, Wv, Wo, w4, nw8);

    // fused QKV GEMM
    gemm_tf32x<<<dim3(12, 54, 3), 256, GEMM_SM>>>(
        xr, w4 + 0 * WSZ, w4 + 1 * WSZ, w4 + 2 * WSZ,
        bq, bk, bv, qp, kp, vp, SEQ, DIM, DIM);

    const float s4 = powf((float)HD, -0.25f);
    norm_rope2<<<dim3(SEQ, 2), 256>>>(qp, kp, gq, gk, fr, s4);
    split_v<<<(SEQ * DIM / 2 + 255) / 256, 256>>>(SEQ * DIM / 2);

    stageA_mma<<<dim3(24, 12, 12), 256, SA_SMEM>>>();
    stageB_mma<<<dim3(24, 12, 12), 256, SB_SMEM>>>();

    round_permute<<<(nx8 + 255) / 256, 256>>>(ap, xr, nx8);
    gemm_tf32x<<<dim3(12, 54, 1), 256, GEMM_SM>>>(
        xr, w4 + 3 * WSZ, w4 + 3 * WSZ, w4 + 3 * WSZ,
        bo, bo, bo, out, out, out, SEQ, DIM, DIM);
}

// round 16
// speedup vs baseline: 1.4161x; 1.4161x over previous
#include <cuda_runtime.h>
#include <cuda_bf16.h>
#include <math.h>
#include <stdint.h>

#define SEQ 6912
#define DIM 1536
#define NH  12
#define HD  128
#define Fg  12
#define Hg  24
#define Wg  24
#define FK  288
#define EPS_NORM 1e-6f
#define CAPF (1.0f/1.000001f)

__device__ float g_q[SEQ * DIM];
__device__ float g_k[SEQ * DIM];
__device__ float g_v[SEQ * DIM];
__device__ float g_attn[SEQ * DIM];
__device__ float g_xr[SEQ * DIM];
__device__ float g_w4[4 * DIM * DIM];
__device__ __nv_bfloat16 g_qh[SEQ * DIM], g_ql[SEQ * DIM];
__device__ __nv_bfloat16 g_kh[SEQ * DIM], g_kl[SEQ * DIM];
__device__ __nv_bfloat16 g_vh[SEQ * DIM], g_vl[SEQ * DIM];
__device__ __nv_bfloat16 g_ah[(size_t)NH * Fg * Wg * FK * HD];
__device__ __nv_bfloat16 g_al[(size_t)NH * Fg * Wg * FK * HD];
__device__ __nv_bfloat16 g_yh[(size_t)NH * Fg * Wg * FK * HD];
__device__ __nv_bfloat16 g_yl[(size_t)NH * Fg * Wg * FK * HD];
__device__ float g_cL[(size_t)NH * Fg * Wg * FK];

__device__ __forceinline__ void cp16(void* dst, const void* src) {
    uint32_t d = (uint32_t)__cvta_generic_to_shared(dst);
    asm volatile("cp.async.cg.shared.global [%0], [%1], 16;\n" :: "r"(d), "l"(src));
}
__device__ __forceinline__ void cp16s(uint32_t dst, const void* src) {
    asm volatile("cp.async.cg.shared.global [%0], [%1], 16;\n" :: "r"(dst), "l"(src));
}
__device__ __forceinline__ float tf32f(float x) {
    uint32_t r;
    asm("cvt.rna.tf32.f32 %0, %1;\n" : "=r"(r) : "f"(x));
    return __uint_as_float(r);
}
__device__ __forceinline__ uint32_t packbf(float a, float b) {
    return (uint32_t)__bfloat16_as_ushort(__float2bfloat16(a)) |
           ((uint32_t)__bfloat16_as_ushort(__float2bfloat16(b)) << 16);
}
__device__ __forceinline__ void split2(float f0, float f1, uint32_t& hi, uint32_t& lo) {
    const __nv_bfloat16 h0 = __float2bfloat16(f0);
    const __nv_bfloat16 h1 = __float2bfloat16(f1);
    hi = (uint32_t)__bfloat16_as_ushort(h0) | ((uint32_t)__bfloat16_as_ushort(h1) << 16);
    lo = packbf(f0 - __bfloat162float(h0), f1 - __bfloat162float(h1));
}

__global__ __launch_bounds__(256) void round_permute(
    const float* __restrict__ in, float* __restrict__ out, int n8)
{
    const int i = blockIdx.x * 256 + threadIdx.x;
    if (i >= n8) return;
    const float4* p = reinterpret_cast<const float4*>(in) + (size_t)i * 2;
    const float4 x0 = p[0], x1 = p[1];
    float4 y0 = make_float4(tf32f(x0.x), tf32f(x1.x), tf32f(x0.y), tf32f(x1.y));
    float4 y1 = make_float4(tf32f(x0.z), tf32f(x1.z), tf32f(x0.w), tf32f(x1.w));
    float4* q = reinterpret_cast<float4*>(out) + (size_t)i * 2;
    q[0] = y0; q[1] = y1;
}

__global__ __launch_bounds__(256) void round_permute_w4(
    const float* __restrict__ W0, const float* __restrict__ W1,
    const float* __restrict__ W2, const float* __restrict__ W3,
    float* __restrict__ out, int n8)
{
    const int t = blockIdx.y;
    const float* src = (t == 0) ? W0 : (t == 1) ? W1 : (t == 2) ? W2 : W3;
    const int i = blockIdx.x * 256 + threadIdx.x;
    if (i >= n8) return;
    const float4* p = reinterpret_cast<const float4*>(src) + (size_t)i * 2;
    const float4 x0 = p[0], x1 = p[1];
    float4 y0 = make_float4(tf32f(x0.x), tf32f(x1.x), tf32f(x0.y), tf32f(x1.y));
    float4 y1 = make_float4(tf32f(x0.z), tf32f(x1.z), tf32f(x0.w), tf32f(x1.w));
    float4* q = reinterpret_cast<float4*>(out + (size_t)t * DIM * DIM) + (size_t)i * 2;
    q[0] = y0; q[1] = y1;
}

__global__ __launch_bounds__(256) void split_v(int n2)
{
    const int i = blockIdx.x * 256 + threadIdx.x;
    if (i >= n2) return;
    const float2 x = reinterpret_cast<const float2*>(g_v)[i];
    uint32_t hi, lo;
    split2(x.x, x.y, hi, lo);
    *reinterpret_cast<uint32_t*>(g_vh + (size_t)i * 2) = hi;
    *reinterpret_cast<uint32_t*>(g_vl + (size_t)i * 2) = lo;
}

// ---- tf32 GEMM, BK=32, dynamic smem, fused over blockIdx.z (up to 3 mats) ---
#define GPAD 40
#define GSTG (128 * GPAD)            // words per array per stage
#define GEMM_SM (4 * GSTG * 4)       // 81920 bytes -> 2 CTAs/SM

__global__ __launch_bounds__(256) void gemm_tf32x(
    const float* __restrict__ A,
    const float* __restrict__ W0, const float* __restrict__ W1,
    const float* __restrict__ W2,
    const float* __restrict__ b0v, const float* __restrict__ b1v,
    const float* __restrict__ b2v,
    float* __restrict__ o0p, float* __restrict__ o1p, float* __restrict__ o2p,
    int M, int K, int O)
{
    extern __shared__ float smf[];
    const int z = blockIdx.z;
    const float* W   = (z == 0) ? W0 : (z == 1) ? W1 : W2;
    const float* bias = (z == 0) ? b0v : (z == 1) ? b1v : b2v;
    float* out = (z == 0) ? o0p : (z == 1) ? o1p : o2p;

    const int tid = threadIdx.x, lane = tid & 31, warp = tid >> 5;
    const int gid = lane >> 2, tg = lane & 3;
    const int wm = (warp & 1) * 64, wn = (warp >> 1) * 32;
    const int m0 = blockIdx.y * 128, o0 = blockIdx.x * 128;

    float acc[4][4][4];
#pragma unroll
    for (int mt = 0; mt < 4; mt++)
#pragma unroll
        for (int nt = 0; nt < 4; nt++)
#pragma unroll
            for (int r = 0; r < 4; r++) acc[mt][nt][r] = 0.f;

    const int nIter = K / 32;    // 48

#define GLOAD(S, IT) do { \
    const int k0 = (IT) * 32; \
    float* As_ = smf + (S) * 2 * GSTG; \
    float* Ws_ = As_ + GSTG; \
    _Pragma("unroll") \
    for (int q = 0; q < 4; q++) { \
        const int idx = tid + q * 256; \
        const int row = idx >> 3, c4 = (idx & 7) * 4; \
        cp16(&As_[row * GPAD + c4], A + (size_t)(m0 + row) * K + k0 + c4); \
        cp16(&Ws_[row * GPAD + c4], W + (size_t)(o0 + row) * K + k0 + c4); \
    } \
    asm volatile("cp.async.commit_group;\n"); \
} while (0)

    GLOAD(0, 0);

    for (int it = 0; it < nIter; ++it) {
        const int b = it & 1;
        if (it + 1 < nIter) {
            GLOAD(b ^ 1, it + 1);
            asm volatile("cp.async.wait_group 1;\n");
        } else {
            asm volatile("cp.async.wait_group 0;\n");
        }
        __syncthreads();
        const float* as = smf + b * 2 * GSTG;
        const float* ws = as + GSTG;
#pragma unroll
        for (int kk = 0; kk < 32; kk += 8) {
            uint32_t a[4][4], bb[4][2];
#pragma unroll
            for (int mt = 0; mt < 4; mt++) {
                const int mr = wm + mt * 16 + gid;
                const float2 pa = *reinterpret_cast<const float2*>(&as[mr * GPAD + kk + 2 * tg]);
                const float2 pb = *reinterpret_cast<const float2*>(&as[(mr + 8) * GPAD + kk + 2 * tg]);
                a[mt][0] = __float_as_uint(pa.x); a[mt][1] = __float_as_uint(pb.x);
                a[mt][2] = __float_as_uint(pa.y); a[mt][3] = __float_as_uint(pb.y);
            }
#pragma unroll
            for (int nt = 0; nt < 4; nt++) {
                const int nr = wn + nt * 8 + gid;
                const float2 pw = *reinterpret_cast<const float2*>(&ws[nr * GPAD + kk + 2 * tg]);
                bb[nt][0] = __float_as_uint(pw.x); bb[nt][1] = __float_as_uint(pw.y);
            }
#pragma unroll
            for (int mt = 0; mt < 4; mt++)
#pragma unroll
                for (int nt = 0; nt < 4; nt++)
                    asm volatile(
                        "mma.sync.aligned.m16n8k8.row.col.f32.tf32.tf32.f32 "
                        "{%0,%1,%2,%3}, {%4,%5,%6,%7}, {%8,%9}, {%0,%1,%2,%3};\n"
                        : "+f"(acc[mt][nt][0]), "+f"(acc[mt][nt][1]),
                          "+f"(acc[mt][nt][2]), "+f"(acc[mt][nt][3])
                        : "r"(a[mt][0]), "r"(a[mt][1]), "r"(a[mt][2]), "r"(a[mt][3]),
                          "r"(bb[nt][0]), "r"(bb[nt][1]));
        }
        __syncthreads();
    }
#pragma unroll
    for (int mt = 0; mt < 4; mt++) {
        const int m = m0 + wm + mt * 16 + gid;
#pragma unroll
        for (int nt = 0; nt < 4; nt++) {
            const int o = o0 + wn + nt * 8 + tg * 2;
            const float c0 = bias[o], c1 = bias[o + 1];
            *reinterpret_cast<float2*>(&out[(size_t)m * O + o]) =
                make_float2(acc[mt][nt][0] + c0, acc[mt][nt][1] + c1);
            *reinterpret_cast<float2*>(&out[(size_t)(m + 8) * O + o]) =
                make_float2(acc[mt][nt][2] + c0, acc[mt][nt][3] + c1);
        }
    }
}

__global__ __launch_bounds__(256) void norm_rope2(
    const float* __restrict__ qd, const float* __restrict__ kd,
    const float* __restrict__ gqv, const float* __restrict__ gkv,
    const float* __restrict__ freqs, float scale)
{
    const int s = blockIdx.x, isK = blockIdx.y;
    const float* row = (isK ? kd : qd) + (size_t)s * DIM;
    __nv_bfloat16* dh = (isK ? g_kh : g_qh) + (size_t)s * DIM;
    __nv_bfloat16* dl = (isK ? g_kl : g_ql) + (size_t)s * DIM;
    const float* g = isK ? gkv : gqv;
    const int tid = threadIdx.x;

    float ss = 0.f;
    for (int c = tid; c < DIM; c += 256) { float v = row[c]; ss += v * v; }
#pragma unroll
    for (int off = 16; off; off >>= 1) ss += __shfl_xor_sync(~0u, ss, off);
    __shared__ float red[8];
    __shared__ float s_rms;
    if ((tid & 31) == 0) red[tid >> 5] = ss;
    __syncthreads();
    if (tid == 0) {
        float t = 0.f;
#pragma unroll
        for (int i = 0; i < 8; i++) t += red[i];
        s_rms = rsqrtf(t / (float)DIM + EPS_NORM);
    }
    __syncthreads();
    const float rms = s_rms;
    const int fidx = s / 576, rem = s % 576, hidx = rem / 24, widx = rem % 24;

    for (int p = tid; p < DIM / 2; p += 256) {
        const int n = p >> 6, m = p & 63;
        const int pos = (m < 22) ? fidx : (m < 43) ? hidx : widx;
        float sn, cs;
        sincosf(freqs[pos * 64 + m], &sn, &cs);
        const int c0 = n * HD + 2 * m;
        const float xr = row[c0] * rms * g[c0];
        const float xi = row[c0 + 1] * rms * g[c0 + 1];
        const float y0 = (xr * cs - xi * sn) * scale;
        const float y1 = (xr * sn + xi * cs) * scale;
        uint32_t hi, lo;
        split2(y0, y1, hi, lo);
        *reinterpret_cast<uint32_t*>(dh + c0) = hi;
        *reinterpret_cast<uint32_t*>(dl + c0) = lo;
    }
}

#define MMAB(C,A0,A1,A2,A3,B0,B1) \
    asm volatile("mma.sync.aligned.m16n8k16.row.col.f32.bf16.bf16.f32 " \
        "{%0,%1,%2,%3}, {%4,%5,%6,%7}, {%8,%9}, {%0,%1,%2,%3};\n" \
        : "+f"((C)[0]), "+f"((C)[1]), "+f"((C)[2]), "+f"((C)[3]) \
        : "r"(A0), "r"(A1), "r"(A2), "r"(A3), "r"(B0), "r"(B1))

#define SA_SMEM (16768 * 4)

__global__ __launch_bounds__(256) void stageA_mma()
{
    const int kb = blockIdx.x, f = blockIdx.y, h = blockIdx.z;
    extern __shared__ uint32_t smw[];
    uint32_t* KH = smw;
    uint32_t* KL = smw + 1632;
    uint32_t* VH = smw + 3264;
    uint32_t* VL = smw + 4896;
    uint32_t* TKH = smw + 6528;
    uint32_t* TKL = smw + 9088;
    uint32_t* TVH = smw + 11648;
    uint32_t* TVL = smw + 14208;

    const int tid = threadIdx.x, lane = tid & 31, w = tid >> 5;
    const int gid = lane >> 2, tg = lane & 3;
    const int skb = f * 576 + kb * 24;

    for (int idx = tid; idx < 24 * 64; idx += 256) {
        const int l = idx >> 6, wd = idx & 63;
        const size_t e = (size_t)(skb + l) * DIM + h * HD + wd * 2;
        KH[l * 68 + wd] = *reinterpret_cast<const uint32_t*>(g_kh + e);
        KL[l * 68 + wd] = *reinterpret_cast<const uint32_t*>(g_kl + e);
        VH[l * 68 + wd] = *reinterpret_cast<const uint32_t*>(g_vh + e);
        VL[l * 68 + wd] = *reinterpret_cast<const uint32_t*>(g_vl + e);
    }
    __syncthreads();
    {
        const ushort* sK = (const ushort*)KH;
        const ushort* sk = (const ushort*)KL;
        const ushort* sV = (const ushort*)VH;
        const ushort* sv = (const ushort*)VL;
        for (int idx = tid; idx < 128 * 12; idx += 256) {
            const int d = idx / 12, wv = idx % 12, l = 2 * wv;
            TKH[d * 20 + wv] = (uint32_t)sK[l * 136 + d] | ((uint32_t)sK[(l + 1) * 136 + d] << 16);
            TKL[d * 20 + wv] = (uint32_t)sk[l * 136 + d] | ((uint32_t)sk[(l + 1) * 136 + d] << 16);
            TVH[d * 20 + wv] = (uint32_t)sV[l * 136 + d] | ((uint32_t)sV[(l + 1) * 136 + d] << 16);
            TVL[d * 20 + wv] = (uint32_t)sv[l * 136 + d] | ((uint32_t)sv[(l + 1) * 136 + d] << 16);
        }
    }
    __syncthreads();

    for (int mt = w; mt < 18; mt += 8) {
        const int r0 = mt * 16 + gid, r1 = r0 + 8;
        const int a0i = r0 / 24, j0 = r0 - a0i * 24;
        const int a1i = r1 / 24, j1 = r1 - a1i * 24;
        const uint32_t* q0h = (const uint32_t*)(g_qh + (size_t)(a0i * 576 + kb * 24 + j0) * DIM + h * HD);
        const uint32_t* q0l = (const uint32_t*)(g_ql + (size_t)(a0i * 576 + kb * 24 + j0) * DIM + h * HD);
        const uint32_t* q1h = (const uint32_t*)(g_qh + (size_t)(a1i * 576 + kb * 24 + j1) * DIM + h * HD);
        const uint32_t* q1l = (const uint32_t*)(g_ql + (size_t)(a1i * 576 + kb * 24 + j1) * DIM + h * HD);

        float c[3][4];
#pragma unroll
        for (int nt = 0; nt < 3; nt++)
            c[nt][0] = c[nt][1] = c[nt][2] = c[nt][3] = 0.f;
#pragma unroll
        for (int kk = 0; kk < 8; kk++) {
            const int wa = kk * 8 + tg;
            const uint32_t ah0 = q0h[wa], ah1 = q1h[wa], ah2 = q0h[wa + 4], ah3 = q1h[wa + 4];
            const uint32_t al0 = q0l[wa], al1 = q1l[wa], al2 = q0l[wa + 4], al3 = q1l[wa + 4];
#pragma unroll
            for (int nt = 0; nt < 3; nt++) {
                const int nb = (nt * 8 + gid) * 68 + wa;
                const uint32_t bh0 = KH[nb], bh1 = KH[nb + 4];
                const uint32_t bl0 = KL[nb], bl1 = KL[nb + 4];
                MMAB(c[nt], ah0, ah1, ah2, ah3, bh0, bh1);
                MMAB(c[nt], ah0, ah1, ah2, ah3, bl0, bl1);
                MMAB(c[nt], al0, al1, al2, al3, bh0, bh1);
            }
        }

        float m0 = -1e30f, m1 = -1e30f;
#pragma unroll
        for (int nt = 0; nt < 3; nt++) {
#pragma unroll
            for (int r = 0; r < 4; r++) c[nt][r] *= CAPF;
            m0 = fmaxf(m0, fmaxf(c[nt][0], c[nt][1]));
            m1 = fmaxf(m1, fmaxf(c[nt][2], c[nt][3]));
        }
        m0 = fmaxf(m0, __shfl_xor_sync(~0u, m0, 1));
        m0 = fmaxf(m0, __shfl_xor_sync(~0u, m0, 2));
        m1 = fmaxf(m1, __shfl_xor_sync(~0u, m1, 1));
        m1 = fmaxf(m1, __shfl_xor_sync(~0u, m1, 2));
        float S0 = 0.f, E0 = 0.f, S1 = 0.f, E1 = 0.f, R[3][4];
#pragma unroll
        for (int nt = 0; nt < 3; nt++) {
            const float t0 = c[nt][0] - m0, t1 = c[nt][1] - m0;
            const float t2 = c[nt][2] - m1, t3 = c[nt][3] - m1;
            const float e0 = expf(t0), e1 = expf(t1), e2 = expf(t2), e3 = expf(t3);
            S0 += e0 + e1; E0 += e0 * t0 + e1 * t1;
            S1 += e2 + e3; E1 += e2 * t2 + e3 * t3;
            R[nt][0] = e0; R[nt][1] = e1; R[nt][2] = e2; R[nt][3] = e3;
        }
        S0 += __shfl_xor_sync(~0u, S0, 1); S0 += __shfl_xor_sync(~0u, S0, 2);
        E0 += __shfl_xor_sync(~0u, E0, 1); E0 += __shfl_xor_sync(~0u, E0, 2);
        S1 += __shfl_xor_sync(~0u, S1, 1); S1 += __shfl_xor_sync(~0u, S1, 2);
        E1 += __shfl_xor_sync(~0u, E1, 1); E1 += __shfl_xor_sync(~0u, E1, 2);
        const float i0 = 1.f / S0, i1 = 1.f / S1;

        const size_t rb0 = ((size_t)((h * 12 + a0i) * 24 + j0)) * FK + (f * 24 + kb);
        const size_t rb1 = ((size_t)((h * 12 + a1i) * 24 + j1)) * FK + (f * 24 + kb);
        if (tg == 0) {
            g_cL[rb0] = E0 * i0 - logf(S0);
            g_cL[rb1] = E1 * i1 - logf(S1);
        }

        uint32_t Ph[3], Pr[3], Ql[3], Qr[3];
#pragma unroll
        for (int nt = 0; nt < 3; nt++) {
            split2(R[nt][0] * i0, R[nt][1] * i0, Ph[nt], Ql[nt]);
            split2(R[nt][2] * i1, R[nt][3] * i1, Pr[nt], Qr[nt]);
        }

        const size_t wb0 = rb0 * 64, wb1 = rb1 * 64;
#pragma unroll
        for (int nt = 0; nt < 16; nt++) {
            const int nb = (nt * 8 + gid) * 20;
            float aa[4] = {0,0,0,0}, ay[4] = {0,0,0,0};
            uint32_t b0 = TKH[nb + tg], b1 = TKH[nb + 4 + tg];
            MMAB(aa, Ph[0], Pr[0], Ph[1], Pr[1], b0, b1);
            MMAB(aa, Ql[0], Qr[0], Ql[1], Qr[1], b0, b1);
            b0 = TKL[nb + tg]; b1 = TKL[nb + 4 + tg];
            MMAB(aa, Ph[0], Pr[0], Ph[1], Pr[1], b0, b1);
            b0 = TKH[nb + 8 + tg];
            MMAB(aa, Ph[2], Pr[2], 0u, 0u, b0, b0);
            MMAB(aa, Ql[2], Qr[2], 0u, 0u, b0, b0);
            b0 = TKL[nb + 8 + tg];
            MMAB(aa, Ph[2], Pr[2], 0u, 0u, b0, b0);

            b0 = TVH[nb + tg]; b1 = TVH[nb + 4 + tg];
            MMAB(ay, Ph[0], Pr[0], Ph[1], Pr[1], b0, b1);
            MMAB(ay, Ql[0], Qr[0], Ql[1], Qr[1], b0, b1);
            b0 = TVL[nb + tg]; b1 = TVL[nb + 4 + tg];
            MMAB(ay, Ph[0], Pr[0], Ph[1], Pr[1], b0, b1);
            b0 = TVH[nb + 8 + tg];
            MMAB(ay, Ph[2], Pr[2], 0u, 0u, b0, b0);
            MMAB(ay, Ql[2], Qr[2], 0u, 0u, b0, b0);
            b0 = TVL[nb + 8 + tg];
            MMAB(ay, Ph[2], Pr[2], 0u, 0u, b0, b0);

            const int wi = nt * 4 + tg;
            uint32_t hi, lo;
            split2(aa[0], aa[1], hi, lo);
            ((uint32_t*)g_ah)[wb0 + wi] = hi; ((uint32_t*)g_al)[wb0 + wi] = lo;
            split2(aa[2], aa[3], hi, lo);
            ((uint32_t*)g_ah)[wb1 + wi] = hi; ((uint32_t*)g_al)[wb1 + wi] = lo;
            split2(ay[0], ay[1], hi, lo);
            ((uint32_t*)g_yh)[wb0 + wi] = hi; ((uint32_t*)g_yl)[wb0 + wi] = lo;
            split2(ay[2], ay[3], hi, lo);
            ((uint32_t*)g_yh)[wb1 + wi] = hi; ((uint32_t*)g_yl)[wb1 + wi] = lo;
        }
    }
}

// ---------------- Stage B (round-14 version, 2 CTAs/SM) ----------------------
#define QHo 0
#define QLo 1632
#define CLo 3264
#define BLo 3552
#define LmHo 10560
#define LmLo 14112
#define Y0H 17664
#define Y0L 19840
#define Y1H 22016
#define Y1L 24192
#define SB_SMEM (26368 * 4)

__global__ __launch_bounds__(256) void stageB_mma()
{
    const int j = blockIdx.x, a = blockIdx.y, h = blockIdx.z;
    extern __shared__ uint32_t smw[];
    uint32_t sb;
    asm("{ .reg .u64 t; cvta.to.shared.u64 t, %1; cvt.u32.u64 %0, t; }"
        : "=r"(sb) : "l"(smw));
    float* bl = (float*)(smw + BLo);
    float* cls = (float*)(smw + CLo);

    const int tid = threadIdx.x, lane = tid & 31, w = tid >> 5;
    const int gid = lane >> 2, tg = lane & 3;
    const size_t base = (size_t)(h * 12 + a) * 24 + j;
    const size_t albase = base * FK * HD;
    const size_t clbase = base * FK;

#define LOADY32(BH, BL2, C) do { \
    _Pragma("unroll") \
    for (int t5 = 0; t5 < 2; t5++) { \
        const int idx = tid + t5 * 256; \
        const int r = idx >> 4, seg = idx & 15; \
        const size_t so = albase + (size_t)((C) * 32 + r) * HD + seg * 8; \
        cp16s(sb + ((BH) + r * 68) * 4 + seg * 16, g_yh + so); \
        cp16s(sb + ((BL2) + r * 68) * 4 + seg * 16, g_yl + so); \
    } \
    asm volatile("cp.async.commit_group;\n"); \
} while (0)

    LOADY32(Y0H, Y0L, 0);

    for (int idx = tid; idx < 24 * 64; idx += 256) {
        const int i = idx >> 6, wd = idx & 63;
        const size_t e = (size_t)(a * 576 + i * 24 + j) * DIM + h * HD + wd * 2;
        smw[QHo + i * 68 + wd] = *reinterpret_cast<const uint32_t*>(g_qh + e);
        smw[QLo + i * 68 + wd] = *reinterpret_cast<const uint32_t*>(g_ql + e);
    }
    for (int idx = tid; idx < FK; idx += 256) cls[idx] = g_cL[clbase + idx];
    __syncthreads();

    for (int mt = w; mt < 18; mt += 8) {
        const int fk0 = mt * 16 + gid, fk1 = fk0 + 8;
        const uint32_t* A0h = (const uint32_t*)g_ah + albase / 2 + fk0 * 64;
        const uint32_t* A0l = (const uint32_t*)g_al + albase / 2 + fk0 * 64;
        const uint32_t* A1h = (const uint32_t*)g_ah + albase / 2 + fk1 * 64;
        const uint32_t* A1l = (const uint32_t*)g_al + albase / 2 + fk1 * 64;

        float c[3][4];
#pragma unroll
        for (int nt = 0; nt < 3; nt++)
            c[nt][0] = c[nt][1] = c[nt][2] = c[nt][3] = 0.f;
#pragma unroll
        for (int kk = 0; kk < 8; kk++) {
            const int wa = kk * 8 + tg;
            const uint32_t ah0 = A0h[wa], ah1 = A1h[wa], ah2 = A0h[wa + 4], ah3 = A1h[wa + 4];
            const uint32_t al0 = A0l[wa], al1 = A1l[wa], al2 = A0l[wa + 4], al3 = A1l[wa + 4];
#pragma unroll
            for (int nt = 0; nt < 3; nt++) {
                const int nb = QHo + (nt * 8 + gid) * 68 + wa;
                const uint32_t bh0 = smw[nb], bh1 = smw[nb + 4];
                const uint32_t bl0 = smw[nb + (QLo - QHo)], bl1 = smw[nb + (QLo - QHo) + 4];
                MMAB(c[nt], ah0, ah1, ah2, ah3, bh0, bh1);
                MMAB(c[nt], ah0, ah1, ah2, ah3, bl0, bl1);
                MMAB(c[nt], al0, al1, al2, al3, bh0, bh1);
            }
        }
        const float cl0 = cls[fk0], cl1 = cls[fk1];
#pragma unroll
        for (int nt = 0; nt < 3; nt++) {
            const int i0 = nt * 8 + 2 * tg;
            bl[i0 * 292 + fk0]       = c[nt][0] - cl0;
            bl[(i0 + 1) * 292 + fk0] = c[nt][1] - cl0;
            bl[i0 * 292 + fk1]       = c[nt][2] - cl1;
            bl[(i0 + 1) * 292 + fk1] = c[nt][3] - cl1;
        }
    }
    __syncthreads();

    for (int ri = w; ri < 24; ri += 8) {
        float* rowp = bl + ri * 292;
        float v[9], mx = -INFINITY;
#pragma unroll
        for (int q = 0; q < 9; q++) { v[q] = rowp[lane + q * 32]; mx = fmaxf(mx, v[q]); }
#pragma unroll
        for (int off = 16; off; off >>= 1) mx = fmaxf(mx, __shfl_xor_sync(~0u, mx, off));
        float s = 0.f;
#pragma unroll
        for (int q = 0; q < 9; q++) { v[q] = expf(v[q] - mx); s += v[q]; }
#pragma unroll
        for (int off = 16; off; off >>= 1) s += __shfl_xor_sync(~0u, s, off);
        const float inv = 1.f / s;
#pragma unroll
        for (int q = 0; q < 9; q++) rowp[lane + q * 32] = v[q] * inv;
        __syncwarp();
        for (int w2 = lane; w2 < 144; w2 += 32) {
            const float f0 = rowp[2 * w2], f1 = rowp[2 * w2 + 1];
            uint32_t hi, lo;
            split2(f0, f1, hi, lo);
            smw[LmHo + ri * 148 + w2] = hi;
            smw[LmLo + ri * 148 + w2] = lo;
        }
    }
    __syncthreads();

    float cc[2][2][4];
#pragma unroll
    for (int m = 0; m < 2; m++)
#pragma unroll
        for (int t = 0; t < 2; t++)
#pragma unroll
            for (int r = 0; r < 4; r++) cc[m][t][r] = 0.f;

#define YCHUNK32(BH, BL2, C) do { \
    _Pragma("unroll") \
    for (int kkl = 0; kkl < 2; kkl++) { \
        const int wa = ((C) * 2 + kkl) * 8 + tg; \
        uint32_t Ah[2][4], Al2[2][4]; \
        _Pragma("unroll") \
        for (int m = 0; m < 2; m++) { \
            int r2w = m * 16 + 8 + gid; if (r2w > 23) r2w = 23; \
            const int rb = (m * 16 + gid) * 148, rb8 = r2w * 148; \
            Ah[m][0] = smw[LmHo + rb + wa];     Ah[m][1] = smw[LmHo + rb8 + wa]; \
            Ah[m][2] = smw[LmHo + rb + wa + 4]; Ah[m][3] = smw[LmHo + rb8 + wa + 4]; \
            Al2[m][0] = smw[LmLo + rb + wa];     Al2[m][1] = smw[LmLo + rb8 + wa]; \
            Al2[m][2] = smw[LmLo + rb + wa + 4]; Al2[m][3] = smw[LmLo + rb8 + wa + 4]; \
        } \
        _Pragma("unroll") \
        for (int t = 0; t < 2; t++) { \
            const int nn = w * 2 + t; \
            const uint32_t ad = sb + ((BH) + (kkl * 16 + (lane & 15)) * 68 + nn * 4) * 4; \
            uint32_t bh0, bh1, bl0, bl1; \
            asm volatile("ldmatrix.sync.aligned.m8n8.x2.trans.shared.b16 {%0,%1}, [%2];" \
                : "=r"(bh0), "=r"(bh1) : "r"(ad)); \
            asm volatile("ldmatrix.sync.aligned.m8n8.x2.trans.shared.b16 {%0,%1}, [%2];" \
                : "=r"(bl0), "=r"(bl1) : "r"(ad + ((BL2) - (BH)) * 4)); \
            _Pragma("unroll") \
            for (int m = 0; m < 2; m++) { \
                MMAB(cc[m][t], Ah[m][0], Ah[m][1], Ah[m][2], Ah[m][3], bh0, bh1); \
                MMAB(cc[m][t], Al2[m][0], Al2[m][1], Al2[m][2], Al2[m][3], bh0, bh1); \
                MMAB(cc[m][t], Ah[m][0], Ah[m][1], Ah[m][2], Ah[m][3], bl0, bl1); \
            } \
        } \
    } \
} while (0)

    LOADY32(Y1H, Y1L, 1);
    for (int c = 0; c < 9; ++c) {
        if (c < 8) { asm volatile("cp.async.wait_group 1;\n"); }
        else       { asm volatile("cp.async.wait_group 0;\n"); }
        __syncthreads();
        if (c & 1) { YCHUNK32(Y1H, Y1L, c); } else { YCHUNK32(Y0H, Y0L, c); }
        __syncthreads();
        if (c + 2 < 9) {
            if (c & 1) { LOADY32(Y1H, Y1L, c + 2); } else { LOADY32(Y0H, Y0L, c + 2); }
        }
    }

#pragma unroll
    for (int t = 0; t < 2; t++) {
        const int d0 = (w * 2 + t) * 8 + 2 * tg;
        const size_t e0 = (size_t)(a * 576 + gid * 24 + j) * DIM + h * HD + d0;
        const size_t e1 = (size_t)(a * 576 + (gid + 8) * 24 + j) * DIM + h * HD + d0;
        const size_t e2 = (size_t)(a * 576 + (gid + 16) * 24 + j) * DIM + h * HD + d0;
        *reinterpret_cast<float2*>(&g_attn[e0]) = make_float2(cc[0][t][0], cc[0][t][1]);
        *reinterpret_cast<float2*>(&g_attn[e1]) = make_float2(cc[0][t][2], cc[0][t][3]);
        *reinterpret_cast<float2*>(&g_attn[e2]) = make_float2(cc[1][t][0], cc[1][t][1]);
    }
}

extern "C" void kernel_launch(void* const* d_in, const int* in_sizes, int n_in,
                              void* d_out, int out_size)
{
    (void)in_sizes; (void)n_in; (void)out_size;
    const float* x  = (const float*)d_in[0];
    const float* Wq = (const float*)d_in[1];
    const float* bq = (const float*)d_in[2];
    const float* Wk = (const float*)d_in[3];
    const float* bk = (const float*)d_in[4];
    const float* Wv = (const float*)d_in[5];
    const float* bv = (const float*)d_in[6];
    const float* Wo = (const float*)d_in[7];
    const float* bo = (const float*)d_in[8];
    const float* gq = (const float*)d_in[9];
    const float* gk = (const float*)d_in[10];
    const float* fr = (const float*)d_in[11];
    float* out = (float*)d_out;

    float *qp, *kp, *vp, *ap, *xr, *w4;
    cudaGetSymbolAddress((void**)&qp, g_q);
    cudaGetSymbolAddress((void**)&kp, g_k);
    cudaGetSymbolAddress((void**)&vp, g_v);
    cudaGetSymbolAddress((void**)&ap, g_attn);
    cudaGetSymbolAddress((void**)&xr, g_xr);
    cudaGetSymbolAddress((void**)&w4, g_w4);

    cudaFuncSetAttribute(gemm_tf32x,
        cudaFuncAttributeMaxDynamicSharedMemorySize, GEMM_SM);
    cudaFuncSetAttribute(stageA_mma,
        cudaFuncAttributeMaxDynamicSharedMemorySize, SA_SMEM);
    cudaFuncSetAttribute(stageB_mma,
        cudaFuncAttributeMaxDynamicSharedMemorySize, SB_SMEM);

    const int nx8 = SEQ * DIM / 8;
    const int nw8 = DIM * DIM / 8;
    const int WSZ = DIM * DIM;

    round_permute<<<(nx8 + 255) / 256, 256>>>(x, xr, nx8);
    round_permute_w4<<<dim3((nw8 + 255) / 256, 4), 256>>>(Wq, Wk, Wv, Wo, w4, nw8);

    // fused QKV GEMM
    gemm_tf32x<<<dim3(12, 54, 3), 256, GEMM_SM>>>(
        xr, w4 + 0 * WSZ, w4 + 1 * WSZ, w4 + 2 * WSZ,
        bq, bk, bv, qp, kp, vp, SEQ, DIM, DIM);

    const float s4 = powf((float)HD, -0.25f);
    norm_rope2<<<dim3(SEQ, 2), 256>>>(qp, kp, gq, gk, fr, s4);
    split_v<<<(SEQ * DIM / 2 + 255) / 256, 256>>>(SEQ * DIM / 2);

    stageA_mma<<<dim3(24, 12, 12), 256, SA_SMEM>>>();
    stageB_mma<<<dim3(24, 12, 12), 256, SB_SMEM>>>();

    round_permute<<<(nx8 + 255) / 256, 256>>>(ap, xr, nx8);
    gemm_tf32x<<<dim3(12, 54, 1), 256, GEMM_SM>>>(
        xr, w4 + 3 * WSZ, w4 + 3 * WSZ, w4 + 3 * WSZ,
        bo, bo, bo, out, out, out, SEQ, DIM, DIM);
}